// round 12
// baseline (speedup 1.0000x reference)
#include <cuda_runtime.h>

#define BQ 64
#define TQ 2048
#define HD 128
#define M_TOTAL (BQ * TQ)
#define CHUNK 8            // xp rows staged per cp.async group
#define NTILE 2048         // 64-row tiles per GEMM
#define NREC 32            // recurrence CTAs (2 batches each)
#define NWORK (148 - NREC) // 116 worker CTAs
#define GRID 148           // == SM count -> wave-1: every CTA solo on its SM

// Scratch for x_proj, padded by 2 chunks so cp.async prefetch can run
// unconditionally past the end (allocation-free rule: __device__ globals).
__device__ float g_xproj[(size_t)M_TOTAL * HD + 2 * CHUNK * HD];
// g_flags[0..NTILE): xproj tile ready; [NTILE..2*NTILE): hidden tile ready
__device__ int g_flags[2 * NTILE];

// ---- packed fp32x2 helpers (sm_100+) ---------------------------------------
__device__ __forceinline__ void ffma2(unsigned long long& d,
                                      unsigned long long a,
                                      unsigned long long b) {
    asm("fma.rn.f32x2 %0, %1, %2, %0;" : "+l"(d) : "l"(a), "l"(b));
}
__device__ __forceinline__ unsigned long long addf2(unsigned long long a,
                                                    unsigned long long b) {
    unsigned long long d;
    asm("add.rn.f32x2 %0, %1, %2;" : "=l"(d) : "l"(a), "l"(b));
    return d;
}
__device__ __forceinline__ unsigned long long pack2(float lo, float hi) {
    unsigned long long p;
    asm("mov.b64 %0, {%1, %2};" : "=l"(p) : "r"(__float_as_uint(lo)), "r"(__float_as_uint(hi)));
    return p;
}
__device__ __forceinline__ void unpack2(unsigned long long p, float& lo, float& hi) {
    unsigned int a, b;
    asm("mov.b64 {%0, %1}, %2;" : "=r"(a), "=r"(b) : "l"(p));
    lo = __uint_as_float(a);
    hi = __uint_as_float(b);
}
__device__ __forceinline__ unsigned int smem_u32(const void* p) {
    unsigned int a;
    asm("{ .reg .u64 t; cvta.to.shared.u64 t, %1; cvt.u32.u64 %0, t; }" : "=r"(a) : "l"(p));
    return a;
}
__device__ __forceinline__ void cp_async16(unsigned int dst, const void* src) {
    asm volatile("cp.async.cg.shared.global [%0], [%1], 16;" :: "r"(dst), "l"(src));
}
__device__ __forceinline__ void cp_commit() {
    asm volatile("cp.async.commit_group;");
}
template <int N> __device__ __forceinline__ void cp_wait() {
    asm volatile("cp.async.wait_group %0;" :: "n"(N));
}

// ---- flag protocol ---------------------------------------------------------
__device__ __forceinline__ void wait_flag(int* f) {
    if (atomicAdd(f, 0) == 0) {
        int backoff = 64;
        do {
            __nanosleep(backoff);
            if (backoff < 2048) backoff <<= 1;
        } while (atomicAdd(f, 0) == 0);
    }
    __threadfence();   // acquire
}

// ---------------------------------------------------------------------------
// GEMM tile: C[m0..m0+64)[n] = sum_k A[m][k]*W[n][k] + bias (+bias2)
// 128 threads, 8m x 8n register tile, FFMA2, K in two 64-chunks (proven).
// pool layout: Wt = pool[0..8192) [k][n] 64x128 ; At = pool[8192..12288) 64x64
// ---------------------------------------------------------------------------
__device__ __forceinline__ void gemm_tile(
    const float* __restrict__ A, const float* __restrict__ W,
    const float* __restrict__ bias, const float* __restrict__ bias2,
    float* __restrict__ C, int m0, float* pool)
{
    float* Wt = pool;
    float* At = pool + 64 * 128;
    const int tid = threadIdx.x;
    const int tx = tid & 15;
    const int ty = tid >> 4;

    unsigned long long acc2[8][4];
#pragma unroll
    for (int i = 0; i < 8; i++)
#pragma unroll
        for (int j = 0; j < 4; j++) acc2[i][j] = 0ull;

#pragma unroll
    for (int kc = 0; kc < 2; kc++) {
#pragma unroll
        for (int r = 0; r < 16; r++) {
            int i  = tid + r * 128;
            int n  = i & 127;
            int k0 = (i >> 7) << 2;
            float4 v = *(const float4*)(W + (size_t)n * 128 + kc * 64 + k0);
            Wt[(k0 + 0) * 128 + n] = v.x;
            Wt[(k0 + 1) * 128 + n] = v.y;
            Wt[(k0 + 2) * 128 + n] = v.z;
            Wt[(k0 + 3) * 128 + n] = v.w;
        }
#pragma unroll
        for (int r = 0; r < 8; r++) {
            int i  = tid + r * 128;
            int m  = i & 63;
            int k0 = (i >> 6) << 2;
            float4 v = *(const float4*)(A + (size_t)(m0 + m) * 128 + kc * 64 + k0);
            At[(k0 + 0) * 64 + m] = v.x;
            At[(k0 + 1) * 64 + m] = v.y;
            At[(k0 + 2) * 64 + m] = v.z;
            At[(k0 + 3) * 64 + m] = v.w;
        }
        __syncthreads();

#pragma unroll 8
        for (int k = 0; k < 64; k++) {
            float4 a0 = *(const float4*)(At + k * 64 + ty * 8);
            float4 a1 = *(const float4*)(At + k * 64 + ty * 8 + 4);
            ulonglong2 w0 = *(const ulonglong2*)(Wt + k * 128 + tx * 4);
            ulonglong2 w1 = *(const ulonglong2*)(Wt + k * 128 + 64 + tx * 4);
            float am[8] = {a0.x, a0.y, a0.z, a0.w, a1.x, a1.y, a1.z, a1.w};
#pragma unroll
            for (int i = 0; i < 8; i++) {
                unsigned long long ad = pack2(am[i], am[i]);
                ffma2(acc2[i][0], ad, w0.x);
                ffma2(acc2[i][1], ad, w0.y);
                ffma2(acc2[i][2], ad, w1.x);
                ffma2(acc2[i][3], ad, w1.y);
            }
        }
        __syncthreads();
    }

    float bb[8];
#pragma unroll
    for (int j = 0; j < 4; j++) {
        bb[j]     = bias[tx * 4 + j];
        bb[4 + j] = bias[64 + tx * 4 + j];
        if (bias2) {
            bb[j]     += bias2[tx * 4 + j];
            bb[4 + j] += bias2[64 + tx * 4 + j];
        }
    }
#pragma unroll
    for (int i = 0; i < 8; i++) {
        const int m = m0 + ty * 8 + i;
        float c[8];
#pragma unroll
        for (int j = 0; j < 4; j++) unpack2(acc2[i][j], c[2 * j], c[2 * j + 1]);
#pragma unroll
        for (int j = 0; j < 8; j++) c[j] += bb[j];
        float* crow = C + (size_t)m * 128;
        *(float4*)(crow + tx * 4)      = make_float4(c[0], c[1], c[2], c[3]);
        *(float4*)(crow + 64 + tx * 4) = make_float4(c[4], c[5], c[6], c[7]);
    }
}

// ---------------------------------------------------------------------------
// Fused persistent kernel, GRID=148 (1 CTA per SM).
//   CTAs [0,NREC):    recurrence, TWO batches per CTA (bA=2c, bB=2c+1).
//                     W_hh row j shared in registers; the two chains'
//                     FFMA2 streams interleave so each chain's serial tail
//                     (exp/reduce/barrier) hides under the other's issue.
//   CTAs [NREC,148):  GEMM workers: all GEMM1 tiles, then GEMM3 gated on
//                     hidden flags.
// Tile index = tblk*64 + b.
// ---------------------------------------------------------------------------
__global__ __launch_bounds__(128, 1) void fused_rnn_kernel(
    const float* __restrict__ seq,  const float* __restrict__ Wih,
    const float* __restrict__ bih,  const float* __restrict__ Whh,
    const float* __restrict__ bhh,  const float* __restrict__ Wout,
    const float* __restrict__ bout, float* __restrict__ xproj,
    float* __restrict__ hid,        float* __restrict__ out)
{
    __shared__ __align__(16) float pool[64 * 128 + 64 * 64];  // 48KB
    const int tid = threadIdx.x;

    if (blockIdx.x >= NREC) {
        // ------------------------- GEMM worker -------------------------
        const int wid = blockIdx.x - NREC;
        for (int tile = wid; tile < NTILE; tile += NWORK) {
            const int bb = tile & 63, tblk = tile >> 6;
            gemm_tile(seq, Wih, bih, bhh, xproj, bb * TQ + tblk * 64, pool);
            __threadfence();
            __syncthreads();
            if (tid == 0) atomicExch(&g_flags[tile], 1);
        }
        for (int tile = wid; tile < NTILE; tile += NWORK) {
            if (tid == 0) wait_flag(&g_flags[NTILE + tile]);
            __syncthreads();
            const int bb = tile & 63, tblk = tile >> 6;
            gemm_tile(hid, Wout, bout, nullptr, out, bb * TQ + tblk * 64, pool);
        }
        return;
    }

    // ---------------- recurrence: two chains per CTA -------------------
    const int bA = blockIdx.x * 2;
    const int bB = bA + 1;

    // pool carve: hA[2][HD] | hB[2][HD] | xpA[2][CHUNK][HD] | xpB[2][CHUNK][HD]
    float* sh_hA  = pool;                         //  1KB
    float* sh_hB  = pool + 2 * HD;                //  1KB
    float* sh_xpA = pool + 4 * HD;                //  8KB
    float* sh_xpB = sh_xpA + 2 * CHUNK * HD;      //  8KB

    // full W_hh row j=tid in registers: 64 packed fp32x2 (shared by chains)
    unsigned long long w2[64];
    {
        const ulonglong2* wp = (const ulonglong2*)(Whh + (size_t)tid * 128);
#pragma unroll
        for (int i = 0; i < 32; i++) {
            ulonglong2 v = wp[i];
            w2[2 * i]     = v.x;
            w2[2 * i + 1] = v.y;
        }
    }

    sh_hA[tid] = 0.f;
    sh_hB[tid] = 0.f;

    const float* xpA = xproj + (size_t)bA * TQ * HD;
    const float* xpB = xproj + (size_t)bB * TQ * HD;
    float* houtA = hid + (size_t)bA * TQ * HD + tid;
    float* houtB = hid + (size_t)bB * TQ * HD + tid;

    // cp.async staging: 4KB/chunk/chain; per thread 32B (2x16B) per chain
    const int cp_row = tid >> 4;
    const int cp_col = (tid & 15) * 8;
    const unsigned int dA0 = smem_u32(sh_xpA + (size_t)cp_row * HD + cp_col);
    const unsigned int dA1 = dA0 + CHUNK * HD * 4;
    const unsigned int dB0 = smem_u32(sh_xpB + (size_t)cp_row * HD + cp_col);
    const unsigned int dB1 = dB0 + CHUNK * HD * 4;
    const float* sA = xpA + (size_t)cp_row * HD + cp_col;
    const float* sB = xpB + (size_t)cp_row * HD + cp_col;

    // first xproj tiles for both batches must be ready
    if (tid == 0) wait_flag(&g_flags[bA]);
    if (tid == 1) wait_flag(&g_flags[bB]);
    __syncthreads();

    // preload chunks 0 and 1 for both chains (group k = chunk k, both chains)
    cp_async16(dA0,      sA);
    cp_async16(dA0 + 16, sA + 4);
    cp_async16(dB0,      sB);
    cp_async16(dB0 + 16, sB + 4);
    cp_commit();
    cp_async16(dA1,      sA + CHUNK * HD);
    cp_async16(dA1 + 16, sA + CHUNK * HD + 4);
    cp_async16(dB1,      sB + CHUNK * HD);
    cp_async16(dB1 + 16, sB + CHUNK * HD + 4);
    cp_commit();

#pragma unroll 1
    for (int tc = 0; tc < TQ / CHUNK; tc++) {
        cp_wait<1>();
        __syncthreads();

        const float* xrowA = sh_xpA + (size_t)(tc & 1) * CHUNK * HD + tid;
        const float* xrowB = sh_xpB + (size_t)(tc & 1) * CHUNK * HD + tid;

#pragma unroll 2
        for (int u = 0; u < CHUNK; u++) {
            const ulonglong2* hpA = (const ulonglong2*)(sh_hA + (u & 1) * HD);
            const ulonglong2* hpB = (const ulonglong2*)(sh_hB + (u & 1) * HD);

            unsigned long long aA[4] = {0ull, 0ull, 0ull, 0ull};
            unsigned long long aB[4] = {0ull, 0ull, 0ull, 0ull};
#pragma unroll
            for (int i = 0; i < 32; i++) {
                ulonglong2 hvA = hpA[i];          // broadcast LDS
                ulonglong2 hvB = hpB[i];
                ffma2(aA[i & 3], hvA.x, w2[2 * i]);
                ffma2(aA[i & 3], hvA.y, w2[2 * i + 1]);
                ffma2(aB[i & 3], hvB.x, w2[2 * i]);
                ffma2(aB[i & 3], hvB.y, w2[2 * i + 1]);
            }
            unsigned long long pA = addf2(addf2(aA[0], aA[1]), addf2(aA[2], aA[3]));
            unsigned long long pB = addf2(addf2(aB[0], aB[1]), addf2(aB[2], aB[3]));
            float loA, hiA, loB, hiB;
            unpack2(pA, loA, hiA);
            unpack2(pB, loB, hiB);

            const float xA = loA + hiA + xrowA[(size_t)u * HD];
            const float xB = loB + hiB + xrowB[(size_t)u * HD];
            // tanh(x) = 1 - 2/(exp(2x)+1)  (~1e-6 rel err); MUFUs pipeline
            const float eA = __expf(2.f * xA);
            const float eB = __expf(2.f * xB);
            const float hA = 1.f - __fdividef(2.f, eA + 1.f);
            const float hB = 1.f - __fdividef(2.f, eB + 1.f);

            sh_hA[((u + 1) & 1) * HD + tid] = hA;
            sh_hB[((u + 1) & 1) * HD + tid] = hB;
            houtA[(size_t)(tc * CHUNK + u) * HD] = hA;
            houtB[(size_t)(tc * CHUNK + u) * HD] = hB;
            __syncthreads();
        }

        // publish hidden tiles every 8 chunks (64 timesteps)
        if ((tc & 7) == 7) {
            __threadfence();
            __syncthreads();
            if (tid == 0) atomicExch(&g_flags[NTILE + (tc >> 3) * 64 + bA], 1);
            if (tid == 1) atomicExch(&g_flags[NTILE + (tc >> 3) * 64 + bB], 1);
        }

        // refill just-consumed buffers with chunk tc+2; gate on producer flags
        {
            const int c2 = tc + 2;
            if ((c2 & 7) == 0 && c2 < TQ / CHUNK) {
                if (tid == 0) wait_flag(&g_flags[(c2 >> 3) * 64 + bA]);
                if (tid == 1) wait_flag(&g_flags[(c2 >> 3) * 64 + bB]);
                __syncthreads();
            }
            const unsigned int dA = (tc & 1) ? dA1 : dA0;
            const unsigned int dB = (tc & 1) ? dB1 : dB0;
            const float* srA = sA + (size_t)c2 * CHUNK * HD;
            const float* srB = sB + (size_t)c2 * CHUNK * HD;
            cp_async16(dA,      srA);
            cp_async16(dA + 16, srA + 4);
            cp_async16(dB,      srB);
            cp_async16(dB + 16, srB + 4);
            cp_commit();
        }
    }
}

// ---------------------------------------------------------------------------
extern "C" void kernel_launch(void* const* d_in, const int* in_sizes, int n_in,
                              void* d_out, int out_size)
{
    const float* seq  = (const float*)d_in[0];
    const float* Wih  = (const float*)d_in[1];
    const float* bih  = (const float*)d_in[2];
    const float* Whh  = (const float*)d_in[3];
    const float* bhh  = (const float*)d_in[4];
    const float* Wout = (const float*)d_in[5];
    const float* bout = (const float*)d_in[6];

    float* hid = (float*)d_out;                  // hidden_states (B,T,H)
    float* out = hid + (size_t)M_TOTAL * HD;     // output_states (B,T,H)

    float* xproj;
    cudaGetSymbolAddress((void**)&xproj, g_xproj);
    void* flags;
    cudaGetSymbolAddress(&flags, g_flags);

    cudaMemsetAsync(flags, 0, 2 * NTILE * sizeof(int));
    fused_rnn_kernel<<<GRID, 128>>>(seq, Wih, bih, Whh, bhh, Wout, bout,
                                    xproj, hid, out);
}

// round 13
// speedup vs baseline: 1.5134x; 1.5134x over previous
#include <cuda_runtime.h>

#define BQ 64
#define TQ 2048
#define HD 128
#define M_TOTAL (BQ * TQ)
#define CHUNK 16           // xp rows staged per cp.async group
#define NTILE 2048         // 64-row tiles per GEMM
#define NREC 64            // recurrence CTAs (1 batch each)
#define NWORK (148 - NREC) // 84 worker CTAs
#define GRID 148           // == SM count -> wave-1: every CTA solo on its SM

// Scratch for x_proj, padded by 2 chunks so cp.async prefetch can run
// unconditionally past the end (allocation-free rule: __device__ globals).
__device__ float g_xproj[(size_t)M_TOTAL * HD + 2 * CHUNK * HD];
// g_flags[0..NTILE): xproj tile ready; [NTILE..2*NTILE): hidden tile ready
__device__ int g_flags[2 * NTILE];

// ---- packed fp32x2 helpers (sm_100+) ---------------------------------------
__device__ __forceinline__ void ffma2(unsigned long long& d,
                                      unsigned long long a,
                                      unsigned long long b) {
    asm("fma.rn.f32x2 %0, %1, %2, %0;" : "+l"(d) : "l"(a), "l"(b));
}
__device__ __forceinline__ unsigned long long addf2(unsigned long long a,
                                                    unsigned long long b) {
    unsigned long long d;
    asm("add.rn.f32x2 %0, %1, %2;" : "=l"(d) : "l"(a), "l"(b));
    return d;
}
__device__ __forceinline__ unsigned long long pack2(float lo, float hi) {
    unsigned long long p;
    asm("mov.b64 %0, {%1, %2};" : "=l"(p) : "r"(__float_as_uint(lo)), "r"(__float_as_uint(hi)));
    return p;
}
__device__ __forceinline__ void unpack2(unsigned long long p, float& lo, float& hi) {
    unsigned int a, b;
    asm("mov.b64 {%0, %1}, %2;" : "=r"(a), "=r"(b) : "l"(p));
    lo = __uint_as_float(a);
    hi = __uint_as_float(b);
}
__device__ __forceinline__ unsigned int smem_u32(const void* p) {
    unsigned int a;
    asm("{ .reg .u64 t; cvta.to.shared.u64 t, %1; cvt.u32.u64 %0, t; }" : "=r"(a) : "l"(p));
    return a;
}
__device__ __forceinline__ void cp_async16(unsigned int dst, const void* src) {
    asm volatile("cp.async.cg.shared.global [%0], [%1], 16;" :: "r"(dst), "l"(src));
}
__device__ __forceinline__ void cp_commit() {
    asm volatile("cp.async.commit_group;");
}
template <int N> __device__ __forceinline__ void cp_wait() {
    asm volatile("cp.async.wait_group %0;" :: "n"(N));
}

// ---- flag protocol ---------------------------------------------------------
__device__ __forceinline__ void wait_flag(int* f) {
    if (atomicAdd(f, 0) == 0) {
        int backoff = 64;
        do {
            __nanosleep(backoff);
            if (backoff < 2048) backoff <<= 1;
        } while (atomicAdd(f, 0) == 0);
    }
    __threadfence();   // acquire
}

// ---------------------------------------------------------------------------
// GEMM tile: C[m0..m0+64)[n] = sum_k A[m][k]*W[n][k] + bias (+bias2)
// 128 threads, 8m x 8n register tile, FFMA2, K in two 64-chunks (proven).
// ---------------------------------------------------------------------------
__device__ __forceinline__ void gemm_tile(
    const float* __restrict__ A, const float* __restrict__ W,
    const float* __restrict__ bias, const float* __restrict__ bias2,
    float* __restrict__ C, int m0, float* pool)
{
    float* Wt = pool;
    float* At = pool + 64 * 128;
    const int tid = threadIdx.x;
    const int tx = tid & 15;
    const int ty = tid >> 4;

    unsigned long long acc2[8][4];
#pragma unroll
    for (int i = 0; i < 8; i++)
#pragma unroll
        for (int j = 0; j < 4; j++) acc2[i][j] = 0ull;

#pragma unroll
    for (int kc = 0; kc < 2; kc++) {
#pragma unroll
        for (int r = 0; r < 16; r++) {
            int i  = tid + r * 128;
            int n  = i & 127;
            int k0 = (i >> 7) << 2;
            float4 v = *(const float4*)(W + (size_t)n * 128 + kc * 64 + k0);
            Wt[(k0 + 0) * 128 + n] = v.x;
            Wt[(k0 + 1) * 128 + n] = v.y;
            Wt[(k0 + 2) * 128 + n] = v.z;
            Wt[(k0 + 3) * 128 + n] = v.w;
        }
#pragma unroll
        for (int r = 0; r < 8; r++) {
            int i  = tid + r * 128;
            int m  = i & 63;
            int k0 = (i >> 6) << 2;
            float4 v = *(const float4*)(A + (size_t)(m0 + m) * 128 + kc * 64 + k0);
            At[(k0 + 0) * 64 + m] = v.x;
            At[(k0 + 1) * 64 + m] = v.y;
            At[(k0 + 2) * 64 + m] = v.z;
            At[(k0 + 3) * 64 + m] = v.w;
        }
        __syncthreads();

#pragma unroll 8
        for (int k = 0; k < 64; k++) {
            float4 a0 = *(const float4*)(At + k * 64 + ty * 8);
            float4 a1 = *(const float4*)(At + k * 64 + ty * 8 + 4);
            ulonglong2 w0 = *(const ulonglong2*)(Wt + k * 128 + tx * 4);
            ulonglong2 w1 = *(const ulonglong2*)(Wt + k * 128 + 64 + tx * 4);
            float am[8] = {a0.x, a0.y, a0.z, a0.w, a1.x, a1.y, a1.z, a1.w};
#pragma unroll
            for (int i = 0; i < 8; i++) {
                unsigned long long ad = pack2(am[i], am[i]);
                ffma2(acc2[i][0], ad, w0.x);
                ffma2(acc2[i][1], ad, w0.y);
                ffma2(acc2[i][2], ad, w1.x);
                ffma2(acc2[i][3], ad, w1.y);
            }
        }
        __syncthreads();
    }

    float bb[8];
#pragma unroll
    for (int j = 0; j < 4; j++) {
        bb[j]     = bias[tx * 4 + j];
        bb[4 + j] = bias[64 + tx * 4 + j];
        if (bias2) {
            bb[j]     += bias2[tx * 4 + j];
            bb[4 + j] += bias2[64 + tx * 4 + j];
        }
    }
#pragma unroll
    for (int i = 0; i < 8; i++) {
        const int m = m0 + ty * 8 + i;
        float c[8];
#pragma unroll
        for (int j = 0; j < 4; j++) unpack2(acc2[i][j], c[2 * j], c[2 * j + 1]);
#pragma unroll
        for (int j = 0; j < 8; j++) c[j] += bb[j];
        float* crow = C + (size_t)m * 128;
        *(float4*)(crow + tx * 4)      = make_float4(c[0], c[1], c[2], c[3]);
        *(float4*)(crow + 64 + tx * 4) = make_float4(c[4], c[5], c[6], c[7]);
    }
}

// ---------------------------------------------------------------------------
// Fused persistent kernel, GRID=148 (1 CTA per SM).
//   CTAs [0,64):    recurrence, one batch each (R11-proven single chain:
//                   thread j owns h[j], W_hh row j in registers, broadcast LDS).
//   CTAs [64,148):  GEMM workers: all GEMM1 tiles (tblk-major), then GEMM3
//                   gated on hidden flags.
// Tile index = tblk*64 + b.
// ---------------------------------------------------------------------------
__global__ __launch_bounds__(128, 1) void fused_rnn_kernel(
    const float* __restrict__ seq,  const float* __restrict__ Wih,
    const float* __restrict__ bih,  const float* __restrict__ Whh,
    const float* __restrict__ bhh,  const float* __restrict__ Wout,
    const float* __restrict__ bout, float* __restrict__ xproj,
    float* __restrict__ hid,        float* __restrict__ out)
{
    __shared__ __align__(16) float pool[64 * 128 + 64 * 64];  // 48KB
    const int tid = threadIdx.x;

    if (blockIdx.x >= NREC) {
        // ------------------------- GEMM worker -------------------------
        const int wid = blockIdx.x - NREC;
        for (int tile = wid; tile < NTILE; tile += NWORK) {
            const int bb = tile & 63, tblk = tile >> 6;
            gemm_tile(seq, Wih, bih, bhh, xproj, bb * TQ + tblk * 64, pool);
            __threadfence();
            __syncthreads();
            if (tid == 0) atomicExch(&g_flags[tile], 1);
        }
        for (int tile = wid; tile < NTILE; tile += NWORK) {
            if (tid == 0) wait_flag(&g_flags[NTILE + tile]);
            __syncthreads();
            const int bb = tile & 63, tblk = tile >> 6;
            gemm_tile(hid, Wout, bout, nullptr, out, bb * TQ + tblk * 64, pool);
        }
        return;
    }

    // --------------------------- recurrence ---------------------------
    const int b = blockIdx.x;
    float* sh_h  = pool;              // [2][HD]   1KB
    float* sh_xp = pool + 2 * HD;     // [2][CHUNK][HD]  16KB

    // full W_hh row j=tid in registers: 64 packed fp32x2
    unsigned long long w2[64];
    {
        const ulonglong2* wp = (const ulonglong2*)(Whh + (size_t)tid * 128);
#pragma unroll
        for (int i = 0; i < 32; i++) {
            ulonglong2 v = wp[i];
            w2[2 * i]     = v.x;
            w2[2 * i + 1] = v.y;
        }
    }

    sh_h[tid] = 0.f;

    const float* xp   = xproj + (size_t)b * TQ * HD;
    float*       hout = hid + (size_t)b * TQ * HD + tid;

    // cp.async staging: 8KB chunk / 128 threads = 64B (4x16B) per thread
    const int cp_row = tid >> 3;          // 0..15
    const int cp_col = (tid & 7) * 16;    // 0..112 step 16
    const unsigned int dst0 = smem_u32(sh_xp + (size_t)cp_row * HD + cp_col);
    const unsigned int dst1 = dst0 + CHUNK * HD * 4;
    const float* src_base = xp + (size_t)cp_row * HD + cp_col;

    // first xproj tile (tblk 0 covers chunks 0..3) must be ready
    if (tid == 0) wait_flag(&g_flags[b]);
    __syncthreads();

#pragma unroll
    for (int q = 0; q < 4; q++) cp_async16(dst0 + q * 16, src_base + q * 4);
    cp_commit();
#pragma unroll
    for (int q = 0; q < 4; q++) cp_async16(dst1 + q * 16, src_base + CHUNK * HD + q * 4);
    cp_commit();

    __syncthreads();  // sh_h init visible

#pragma unroll 1
    for (int tc = 0; tc < TQ / CHUNK; tc++) {
        cp_wait<1>();
        __syncthreads();

        const float* xrow = sh_xp + (size_t)(tc & 1) * CHUNK * HD + tid;

#pragma unroll 2
        for (int u = 0; u < CHUNK; u++) {
            // xp value: independent of h, issue first (off critical path)
            const float xv = *xrow;
            xrow += HD;

            const ulonglong2* hp = (const ulonglong2*)(sh_h + (u & 1) * HD);
            unsigned long long a2[4] = {0ull, 0ull, 0ull, 0ull};
#pragma unroll
            for (int i = 0; i < 32; i++) {
                ulonglong2 hv = hp[i];           // broadcast LDS
                ffma2(a2[i & 3], hv.x, w2[2 * i]);
                ffma2(a2[i & 3], hv.y, w2[2 * i + 1]);
            }
            unsigned long long p = addf2(addf2(a2[0], a2[1]), addf2(a2[2], a2[3]));
            float lo, hi;
            unpack2(p, lo, hi);

            const float x = lo + hi + xv;
            // tanh(x) = 1 - 2*rcp(exp2(x*2log2e) + 1)   (~1e-6 rel err)
            const float e = exp2f(x * 2.885390081777927f);  // MUFU.EX2 + 1 mul
            float r;
            asm("rcp.approx.f32 %0, %1;" : "=f"(r) : "f"(e + 1.f));
            const float hn = fmaf(-2.f, r, 1.f);

            sh_h[((u + 1) & 1) * HD + tid] = hn;
            *hout = hn;
            hout += HD;
            __syncthreads();
        }

        // publish hidden tile every 4 chunks (64 timesteps)
        if ((tc & 3) == 3) {
            __threadfence();
            __syncthreads();
            if (tid == 0) atomicExch(&g_flags[NTILE + (tc >> 2) * 64 + b], 1);
        }

        // refill just-consumed buffer with chunk tc+2; gate on producer flag
        {
            const int c2 = tc + 2;
            if ((c2 & 3) == 0 && c2 < TQ / CHUNK) {
                if (tid == 0) wait_flag(&g_flags[(c2 >> 2) * 64 + b]);
                __syncthreads();
            }
            const unsigned int d = (tc & 1) ? dst1 : dst0;
            const float* s = src_base + (size_t)c2 * CHUNK * HD;
#pragma unroll
            for (int q = 0; q < 4; q++) cp_async16(d + q * 16, s + q * 4);
            cp_commit();
        }
    }
}

// ---------------------------------------------------------------------------
extern "C" void kernel_launch(void* const* d_in, const int* in_sizes, int n_in,
                              void* d_out, int out_size)
{
    const float* seq  = (const float*)d_in[0];
    const float* Wih  = (const float*)d_in[1];
    const float* bih  = (const float*)d_in[2];
    const float* Whh  = (const float*)d_in[3];
    const float* bhh  = (const float*)d_in[4];
    const float* Wout = (const float*)d_in[5];
    const float* bout = (const float*)d_in[6];

    float* hid = (float*)d_out;                  // hidden_states (B,T,H)
    float* out = hid + (size_t)M_TOTAL * HD;     // output_states (B,T,H)

    float* xproj;
    cudaGetSymbolAddress((void**)&xproj, g_xproj);
    void* flags;
    cudaGetSymbolAddress(&flags, g_flags);

    cudaMemsetAsync(flags, 0, 2 * NTILE * sizeof(int));
    fused_rnn_kernel<<<GRID, 128>>>(seq, Wih, bih, Whh, bhh, Wout, bout,
                                    xproj, hid, out);
}

// round 14
// speedup vs baseline: 1.5365x; 1.0153x over previous
#include <cuda_runtime.h>

#define BQ 64
#define TQ 2048
#define HD 128
#define M_TOTAL (BQ * TQ)
#define CHUNK 8            // xp rows staged per cp.async group
#define NTILE 2048         // 64-row tiles per GEMM
#define NREC 64            // recurrence CTAs (1 batch each)
#define NWORK (148 - NREC) // 84 worker CTAs
#define GRID 148           // == SM count -> wave-1: every CTA solo on its SM

// Scratch for x_proj, padded by 2 chunks so cp.async prefetch can run
// unconditionally past the end (allocation-free rule: __device__ globals).
__device__ float g_xproj[(size_t)M_TOTAL * HD + 2 * CHUNK * HD];
// g_flags[0..NTILE): xproj tile ready; [NTILE..2*NTILE): hidden tile ready
__device__ int g_flags[2 * NTILE];

// ---- packed fp32x2 helpers (sm_100+) ---------------------------------------
__device__ __forceinline__ void ffma2(unsigned long long& d,
                                      unsigned long long a,
                                      unsigned long long b) {
    asm("fma.rn.f32x2 %0, %1, %2, %0;" : "+l"(d) : "l"(a), "l"(b));
}
__device__ __forceinline__ unsigned long long addf2(unsigned long long a,
                                                    unsigned long long b) {
    unsigned long long d;
    asm("add.rn.f32x2 %0, %1, %2;" : "=l"(d) : "l"(a), "l"(b));
    return d;
}
__device__ __forceinline__ unsigned long long pack2(float lo, float hi) {
    unsigned long long p;
    asm("mov.b64 %0, {%1, %2};" : "=l"(p) : "r"(__float_as_uint(lo)), "r"(__float_as_uint(hi)));
    return p;
}
__device__ __forceinline__ void unpack2(unsigned long long p, float& lo, float& hi) {
    unsigned int a, b;
    asm("mov.b64 {%0, %1}, %2;" : "=r"(a), "=r"(b) : "l"(p));
    lo = __uint_as_float(a);
    hi = __uint_as_float(b);
}
__device__ __forceinline__ unsigned int smem_u32(const void* p) {
    unsigned int a;
    asm("{ .reg .u64 t; cvta.to.shared.u64 t, %1; cvt.u32.u64 %0, t; }" : "=r"(a) : "l"(p));
    return a;
}
__device__ __forceinline__ void cp_async16(unsigned int dst, const void* src) {
    asm volatile("cp.async.cg.shared.global [%0], [%1], 16;" :: "r"(dst), "l"(src));
}
__device__ __forceinline__ void cp_commit() {
    asm volatile("cp.async.commit_group;");
}
template <int N> __device__ __forceinline__ void cp_wait() {
    asm volatile("cp.async.wait_group %0;" :: "n"(N));
}
// Split named barrier (id 1, count 256 = 128 arrives + 128 syncs per phase)
__device__ __forceinline__ void bar1_arrive() {
    asm volatile("bar.arrive 1, 256;" ::: "memory");
}
__device__ __forceinline__ void bar1_sync() {
    asm volatile("bar.sync 1, 256;" ::: "memory");
}

// ---- flag protocol ---------------------------------------------------------
__device__ __forceinline__ void wait_flag(int* f) {
    if (atomicAdd(f, 0) == 0) {
        int backoff = 64;
        do {
            __nanosleep(backoff);
            if (backoff < 2048) backoff <<= 1;
        } while (atomicAdd(f, 0) == 0);
    }
    __threadfence();   // acquire
}

// ---------------------------------------------------------------------------
// GEMM tile: C[m0..m0+64)[n] = sum_k A[m][k]*W[n][k] + bias (+bias2)
// 128 threads, 8m x 8n register tile, FFMA2, K in two 64-chunks (proven).
// ---------------------------------------------------------------------------
__device__ __forceinline__ void gemm_tile(
    const float* __restrict__ A, const float* __restrict__ W,
    const float* __restrict__ bias, const float* __restrict__ bias2,
    float* __restrict__ C, int m0, float* pool)
{
    float* Wt = pool;
    float* At = pool + 64 * 128;
    const int tid = threadIdx.x;
    const int tx = tid & 15;
    const int ty = tid >> 4;

    unsigned long long acc2[8][4];
#pragma unroll
    for (int i = 0; i < 8; i++)
#pragma unroll
        for (int j = 0; j < 4; j++) acc2[i][j] = 0ull;

#pragma unroll
    for (int kc = 0; kc < 2; kc++) {
#pragma unroll
        for (int r = 0; r < 16; r++) {
            int i  = tid + r * 128;
            int n  = i & 127;
            int k0 = (i >> 7) << 2;
            float4 v = *(const float4*)(W + (size_t)n * 128 + kc * 64 + k0);
            Wt[(k0 + 0) * 128 + n] = v.x;
            Wt[(k0 + 1) * 128 + n] = v.y;
            Wt[(k0 + 2) * 128 + n] = v.z;
            Wt[(k0 + 3) * 128 + n] = v.w;
        }
#pragma unroll
        for (int r = 0; r < 8; r++) {
            int i  = tid + r * 128;
            int m  = i & 63;
            int k0 = (i >> 6) << 2;
            float4 v = *(const float4*)(A + (size_t)(m0 + m) * 128 + kc * 64 + k0);
            At[(k0 + 0) * 64 + m] = v.x;
            At[(k0 + 1) * 64 + m] = v.y;
            At[(k0 + 2) * 64 + m] = v.z;
            At[(k0 + 3) * 64 + m] = v.w;
        }
        __syncthreads();

#pragma unroll 8
        for (int k = 0; k < 64; k++) {
            float4 a0 = *(const float4*)(At + k * 64 + ty * 8);
            float4 a1 = *(const float4*)(At + k * 64 + ty * 8 + 4);
            ulonglong2 w0 = *(const ulonglong2*)(Wt + k * 128 + tx * 4);
            ulonglong2 w1 = *(const ulonglong2*)(Wt + k * 128 + 64 + tx * 4);
            float am[8] = {a0.x, a0.y, a0.z, a0.w, a1.x, a1.y, a1.z, a1.w};
#pragma unroll
            for (int i = 0; i < 8; i++) {
                unsigned long long ad = pack2(am[i], am[i]);
                ffma2(acc2[i][0], ad, w0.x);
                ffma2(acc2[i][1], ad, w0.y);
                ffma2(acc2[i][2], ad, w1.x);
                ffma2(acc2[i][3], ad, w1.y);
            }
        }
        __syncthreads();
    }

    float bb[8];
#pragma unroll
    for (int j = 0; j < 4; j++) {
        bb[j]     = bias[tx * 4 + j];
        bb[4 + j] = bias[64 + tx * 4 + j];
        if (bias2) {
            bb[j]     += bias2[tx * 4 + j];
            bb[4 + j] += bias2[64 + tx * 4 + j];
        }
    }
#pragma unroll
    for (int i = 0; i < 8; i++) {
        const int m = m0 + ty * 8 + i;
        float c[8];
#pragma unroll
        for (int j = 0; j < 4; j++) unpack2(acc2[i][j], c[2 * j], c[2 * j + 1]);
#pragma unroll
        for (int j = 0; j < 8; j++) c[j] += bb[j];
        float* crow = C + (size_t)m * 128;
        *(float4*)(crow + tx * 4)      = make_float4(c[0], c[1], c[2], c[3]);
        *(float4*)(crow + 64 + tx * 4) = make_float4(c[4], c[5], c[6], c[7]);
    }
}

// ---------------------------------------------------------------------------
// Fused persistent kernel, GRID=148 (1 CTA per SM).
//   CTAs [0,64):    recurrence, one batch each. R11 body + split-barrier:
//                   each thread's dot is ROTATED so its own warp's 32 k come
//                   first (visible via syncwarp); bar.arrive/bar.sync hides
//                   the CTA barrier drain under the own-range partial dot.
//                   h stored MIRRORED ([j] and [j+128]) so the rotated read
//                   is linear (no wraparound), still broadcast.
//   CTAs [64,148):  GEMM workers: all GEMM1 tiles, then GEMM3 gated on flags.
// ---------------------------------------------------------------------------
__global__ __launch_bounds__(128, 1) void fused_rnn_kernel(
    const float* __restrict__ seq,  const float* __restrict__ Wih,
    const float* __restrict__ bih,  const float* __restrict__ Whh,
    const float* __restrict__ bhh,  const float* __restrict__ Wout,
    const float* __restrict__ bout, float* __restrict__ xproj,
    float* __restrict__ hid,        float* __restrict__ out)
{
    __shared__ __align__(16) float pool[64 * 128 + 64 * 64];  // 48KB
    const int tid = threadIdx.x;

    if (blockIdx.x >= NREC) {
        // ------------------------- GEMM worker -------------------------
        const int wid = blockIdx.x - NREC;
        for (int tile = wid; tile < NTILE; tile += NWORK) {
            const int bb = tile & 63, tblk = tile >> 6;
            gemm_tile(seq, Wih, bih, bhh, xproj, bb * TQ + tblk * 64, pool);
            __threadfence();
            __syncthreads();
            if (tid == 0) atomicExch(&g_flags[tile], 1);
        }
        for (int tile = wid; tile < NTILE; tile += NWORK) {
            if (tid == 0) wait_flag(&g_flags[NTILE + tile]);
            __syncthreads();
            const int bb = tile & 63, tblk = tile >> 6;
            gemm_tile(hid, Wout, bout, nullptr, out, bb * TQ + tblk * 64, pool);
        }
        return;
    }

    // --------------------------- recurrence ---------------------------
    const int b    = blockIdx.x;
    const int rot8 = (tid >> 5) * 8;      // own warp's first ulonglong2 chunk
    float* sh_h  = pool;                  // [2][256] floats (mirrored), 2KB
    float* sh_xp = pool + 2 * 256;        // [2][CHUNK][HD], 8KB

    // W_hh row j=tid in registers, ROTATED: w2[2m],w2[2m+1] pair with h-chunk
    // (rot8+m) mod 32 (each chunk = 4 consecutive k = one ulonglong2).
    unsigned long long w2[64];
    {
        const ulonglong2* wp = (const ulonglong2*)(Whh + (size_t)tid * 128);
#pragma unroll
        for (int m = 0; m < 32; m++) {
            ulonglong2 v = wp[(rot8 + m) & 31];
            w2[2 * m]     = v.x;
            w2[2 * m + 1] = v.y;
        }
    }

    // init h_{-1} = 0 in parity-0 buffer (both copies)
    sh_h[tid]       = 0.f;
    sh_h[128 + tid] = 0.f;

    const float* xp   = xproj + (size_t)b * TQ * HD;
    float*       hout = hid + (size_t)b * TQ * HD + tid;

    // cp.async staging: 4KB chunk / 128 threads = 32B (2x16B) per thread
    const int cp_row = tid >> 4;
    const int cp_col = (tid & 15) * 8;
    const unsigned int dst0 = smem_u32(sh_xp + (size_t)cp_row * HD + cp_col);
    const unsigned int dst1 = dst0 + CHUNK * HD * 4;
    const float* src_base = xp + (size_t)cp_row * HD + cp_col;

    // first xproj tile (tblk 0) must be ready before preloading chunks 0,1
    if (tid == 0) wait_flag(&g_flags[b]);
    __syncthreads();

    cp_async16(dst0,      src_base);
    cp_async16(dst0 + 16, src_base + 4);
    cp_commit();
    cp_async16(dst1,      src_base + CHUNK * HD);
    cp_async16(dst1 + 16, src_base + CHUNK * HD + 4);
    cp_commit();

    __syncthreads();     // h init visible CTA-wide
    bar1_arrive();       // seed: first step's bar1_sync pairs with this

#pragma unroll 1
    for (int tc = 0; tc < TQ / CHUNK; tc++) {
        cp_wait<1>();
        __syncthreads();

        const float* xrow = sh_xp + (size_t)(tc & 1) * CHUNK * HD + tid;

#pragma unroll 2
        for (int u = 0; u < CHUNK; u++) {
            const float xv = xrow[(size_t)u * HD];   // independent of h

            // rotated linear read base: chunks rot8 .. rot8+31 of mirrored buf
            const ulonglong2* hp =
                (const ulonglong2*)(sh_h + (u & 1) * 256) + rot8;

            unsigned long long a2[4] = {0ull, 0ull, 0ull, 0ull};
            // own warp's 32 k (chunks rot8..rot8+7): visible via syncwarp,
            // no CTA barrier needed -> overlaps the barrier drain.
#pragma unroll
            for (int m = 0; m < 8; m++) {
                ulonglong2 hv = hp[m];
                ffma2(a2[m & 3], hv.x, w2[2 * m]);
                ffma2(a2[m & 3], hv.y, w2[2 * m + 1]);
            }
            bar1_sync();   // acquire: all warps' h of this parity published
#pragma unroll
            for (int m = 8; m < 32; m++) {
                ulonglong2 hv = hp[m];
                ffma2(a2[m & 3], hv.x, w2[2 * m]);
                ffma2(a2[m & 3], hv.y, w2[2 * m + 1]);
            }
            unsigned long long p = addf2(addf2(a2[0], a2[1]), addf2(a2[2], a2[3]));
            float lo, hi;
            unpack2(p, lo, hi);

            const float x = lo + hi + xv;
            // tanh(x) = 1 - 2/(exp(2x)+1)   (~1e-6 rel err)
            const float e  = __expf(2.f * x);
            const float hn = 1.f - __fdividef(2.f, e + 1.f);

            // publish: mirrored store, own-warp visibility via syncwarp,
            // CTA visibility via release-arrive.
            float* wbuf = sh_h + ((u + 1) & 1) * 256;
            wbuf[tid]       = hn;
            wbuf[128 + tid] = hn;
            hout[(size_t)(tc * CHUNK + u) * HD] = hn;
            __syncwarp();
            bar1_arrive();
        }

        // publish hidden tile every 8 chunks (64 timesteps)
        if ((tc & 7) == 7) {
            __threadfence();
            __syncthreads();
            if (tid == 0) atomicExch(&g_flags[NTILE + (tc >> 3) * 64 + b], 1);
        }

        // refill just-consumed buffer with chunk tc+2; gate on producer flag
        {
            const int c2 = tc + 2;
            if ((c2 & 7) == 0 && c2 < TQ / CHUNK) {
                if (tid == 0) wait_flag(&g_flags[(c2 >> 3) * 64 + b]);
                __syncthreads();
            }
            const unsigned int d = (tc & 1) ? dst1 : dst0;
            const float* s = src_base + (size_t)c2 * CHUNK * HD;
            cp_async16(d,      s);
            cp_async16(d + 16, s + 4);
            cp_commit();
        }
    }
}

// ---------------------------------------------------------------------------
extern "C" void kernel_launch(void* const* d_in, const int* in_sizes, int n_in,
                              void* d_out, int out_size)
{
    const float* seq  = (const float*)d_in[0];
    const float* Wih  = (const float*)d_in[1];
    const float* bih  = (const float*)d_in[2];
    const float* Whh  = (const float*)d_in[3];
    const float* bhh  = (const float*)d_in[4];
    const float* Wout = (const float*)d_in[5];
    const float* bout = (const float*)d_in[6];

    float* hid = (float*)d_out;                  // hidden_states (B,T,H)
    float* out = hid + (size_t)M_TOTAL * HD;     // output_states (B,T,H)

    float* xproj;
    cudaGetSymbolAddress((void**)&xproj, g_xproj);
    void* flags;
    cudaGetSymbolAddress(&flags, g_flags);

    cudaMemsetAsync(flags, 0, 2 * NTILE * sizeof(int));
    fused_rnn_kernel<<<GRID, 128>>>(seq, Wih, bih, Whh, bhh, Wout, bout,
                                    xproj, hid, out);
}

// round 16
// speedup vs baseline: 1.5443x; 1.0050x over previous
#include <cuda_runtime.h>

#define BQ 64
#define TQ 2048
#define HD 128
#define M_TOTAL (BQ * TQ)
#define CHUNK 8            // xp rows staged per cp.async group
#define NTILE 2048         // 64-row tiles per GEMM
#define NREC 64            // recurrence CTAs (1 batch each)
#define NWORK (148 - NREC) // 84 worker CTAs
#define GRID 148           // == SM count -> wave-1: every CTA solo on its SM

__device__ float g_xproj[(size_t)M_TOTAL * HD + 2 * CHUNK * HD];
// g_flags[0..NTILE): xproj tile ready; [NTILE..2*NTILE): hidden tile ready
__device__ int g_flags[2 * NTILE];

// ---- packed fp32x2 helpers (sm_100+) ---------------------------------------
__device__ __forceinline__ void ffma2(unsigned long long& d,
                                      unsigned long long a,
                                      unsigned long long b) {
    asm("fma.rn.f32x2 %0, %1, %2, %0;" : "+l"(d) : "l"(a), "l"(b));
}
__device__ __forceinline__ unsigned long long addf2(unsigned long long a,
                                                    unsigned long long b) {
    unsigned long long d;
    asm("add.rn.f32x2 %0, %1, %2;" : "=l"(d) : "l"(a), "l"(b));
    return d;
}
__device__ __forceinline__ unsigned long long pack2(float lo, float hi) {
    unsigned long long p;
    asm("mov.b64 %0, {%1, %2};" : "=l"(p) : "r"(__float_as_uint(lo)), "r"(__float_as_uint(hi)));
    return p;
}
__device__ __forceinline__ void unpack2(unsigned long long p, float& lo, float& hi) {
    unsigned int a, b;
    asm("mov.b64 {%0, %1}, %2;" : "=r"(a), "=r"(b) : "l"(p));
    lo = __uint_as_float(a);
    hi = __uint_as_float(b);
}
__device__ __forceinline__ unsigned int smem_u32(const void* p) {
    unsigned int a;
    asm("{ .reg .u64 t; cvta.to.shared.u64 t, %1; cvt.u32.u64 %0, t; }" : "=r"(a) : "l"(p));
    return a;
}
__device__ __forceinline__ void cp_async16(unsigned int dst, const void* src) {
    asm volatile("cp.async.cg.shared.global [%0], [%1], 16;" :: "r"(dst), "l"(src));
}
__device__ __forceinline__ void cp_commit() {
    asm volatile("cp.async.commit_group;");
}
template <int N> __device__ __forceinline__ void cp_wait() {
    asm volatile("cp.async.wait_group %0;" :: "n"(N));
}

// ---- flag protocol ---------------------------------------------------------
__device__ __forceinline__ void wait_flag(int* f) {
    if (atomicAdd(f, 0) == 0) {
        int backoff = 64;
        do {
            __nanosleep(backoff);
            if (backoff < 2048) backoff <<= 1;
        } while (atomicAdd(f, 0) == 0);
    }
    __threadfence();   // acquire
}

// ---------------------------------------------------------------------------
// GEMM tile: C[m0..m0+64)[n] = sum_k A[m][k]*W[n][k] + bias (+bias2)
// 256 threads (2 warps/SMSP for latency hiding), 4m x 8n register tile,
// FFMA2, K in two 64-chunks.
// ---------------------------------------------------------------------------
__device__ __forceinline__ void gemm_tile(
    const float* __restrict__ A, const float* __restrict__ W,
    const float* __restrict__ bias, const float* __restrict__ bias2,
    float* __restrict__ C, int m0, float* pool)
{
    float* Wt = pool;             // [k][n] 64x128
    float* At = pool + 64 * 128;  // [k][m] 64x64
    const int tid = threadIdx.x;
    const int tx = tid & 15;      // n: cols tx*4..+3 and 64+tx*4..+3
    const int ty = tid >> 4;      // m: rows ty*4..+3   (ty in 0..15)

    unsigned long long acc2[4][4];
#pragma unroll
    for (int i = 0; i < 4; i++)
#pragma unroll
        for (int j = 0; j < 4; j++) acc2[i][j] = 0ull;

#pragma unroll
    for (int kc = 0; kc < 2; kc++) {
#pragma unroll
        for (int r = 0; r < 8; r++) {
            int i  = tid + r * 256;
            int n  = i & 127;
            int k0 = (i >> 7) << 2;
            float4 v = *(const float4*)(W + (size_t)n * 128 + kc * 64 + k0);
            Wt[(k0 + 0) * 128 + n] = v.x;
            Wt[(k0 + 1) * 128 + n] = v.y;
            Wt[(k0 + 2) * 128 + n] = v.z;
            Wt[(k0 + 3) * 128 + n] = v.w;
        }
#pragma unroll
        for (int r = 0; r < 4; r++) {
            int i  = tid + r * 256;
            int m  = i & 63;
            int k0 = (i >> 6) << 2;
            float4 v = *(const float4*)(A + (size_t)(m0 + m) * 128 + kc * 64 + k0);
            At[(k0 + 0) * 64 + m] = v.x;
            At[(k0 + 1) * 64 + m] = v.y;
            At[(k0 + 2) * 64 + m] = v.z;
            At[(k0 + 3) * 64 + m] = v.w;
        }
        __syncthreads();

#pragma unroll 8
        for (int k = 0; k < 64; k++) {
            float4 a = *(const float4*)(At + k * 64 + ty * 4);
            ulonglong2 w0 = *(const ulonglong2*)(Wt + k * 128 + tx * 4);
            ulonglong2 w1 = *(const ulonglong2*)(Wt + k * 128 + 64 + tx * 4);
            float am[4] = {a.x, a.y, a.z, a.w};
#pragma unroll
            for (int i = 0; i < 4; i++) {
                unsigned long long ad = pack2(am[i], am[i]);
                ffma2(acc2[i][0], ad, w0.x);
                ffma2(acc2[i][1], ad, w0.y);
                ffma2(acc2[i][2], ad, w1.x);
                ffma2(acc2[i][3], ad, w1.y);
            }
        }
        __syncthreads();
    }

    float bb[8];
#pragma unroll
    for (int j = 0; j < 4; j++) {
        bb[j]     = bias[tx * 4 + j];
        bb[4 + j] = bias[64 + tx * 4 + j];
        if (bias2) {
            bb[j]     += bias2[tx * 4 + j];
            bb[4 + j] += bias2[64 + tx * 4 + j];
        }
    }
#pragma unroll
    for (int i = 0; i < 4; i++) {
        const int m = m0 + ty * 4 + i;
        float c[8];
#pragma unroll
        for (int j = 0; j < 4; j++) unpack2(acc2[i][j], c[2 * j], c[2 * j + 1]);
#pragma unroll
        for (int j = 0; j < 8; j++) c[j] += bb[j];
        float* crow = C + (size_t)m * 128;
        *(float4*)(crow + tx * 4)      = make_float4(c[0], c[1], c[2], c[3]);
        *(float4*)(crow + 64 + tx * 4) = make_float4(c[4], c[5], c[6], c[7]);
    }
}

// ---------------------------------------------------------------------------
// Fused persistent kernel, GRID=148, 256 threads.
//   CTAs [0,64):    recurrence. Warps 0-3 compute (R11 body: thread j owns
//                   h[j], W_hh row in regs, broadcast LDS). Warps 4-7 are
//                   HELPERS: hout STG (one step behind), cp.async staging,
//                   fences + flags — all off the serial critical path.
//   CTAs [64,148):  GEMM workers (256-thread tiles).
// ---------------------------------------------------------------------------
__global__ __launch_bounds__(256, 1) void fused_rnn_kernel(
    const float* __restrict__ seq,  const float* __restrict__ Wih,
    const float* __restrict__ bih,  const float* __restrict__ Whh,
    const float* __restrict__ bhh,  const float* __restrict__ Wout,
    const float* __restrict__ bout, float* __restrict__ xproj,
    float* __restrict__ hid,        float* __restrict__ out)
{
    __shared__ __align__(16) float pool[64 * 128 + 64 * 64];  // 48KB
    const int tid = threadIdx.x;

    if (blockIdx.x >= NREC) {
        // ------------------------- GEMM worker -------------------------
        const int wid = blockIdx.x - NREC;
        for (int tile = wid; tile < NTILE; tile += NWORK) {
            const int bb = tile & 63, tblk = tile >> 6;
            gemm_tile(seq, Wih, bih, bhh, xproj, bb * TQ + tblk * 64, pool);
            __threadfence();
            __syncthreads();
            if (tid == 0) atomicExch(&g_flags[tile], 1);
        }
        for (int tile = wid; tile < NTILE; tile += NWORK) {
            if (tid == 0) wait_flag(&g_flags[NTILE + tile]);
            __syncthreads();
            const int bb = tile & 63, tblk = tile >> 6;
            gemm_tile(hid, Wout, bout, nullptr, out, bb * TQ + tblk * 64, pool);
        }
        return;
    }

    // --------------------------- recurrence ---------------------------
    const int b = blockIdx.x;
    float* sh_h  = pool;              // [2][HD]  1KB
    float* sh_xp = pool + 2 * HD;     // [2][CHUNK][HD]  8KB

    unsigned long long w2[64];        // compute warps only
    if (tid < 128) {
        const ulonglong2* wp = (const ulonglong2*)(Whh + (size_t)tid * 128);
#pragma unroll
        for (int i = 0; i < 32; i++) {
            ulonglong2 v = wp[i];
            w2[2 * i]     = v.x;
            w2[2 * i + 1] = v.y;
        }
        sh_h[tid] = 0.f;
    }

    const float* xp = xproj + (size_t)b * TQ * HD;
    float* hst = hid + (size_t)b * TQ * HD + (tid & 127);

    // helper cp.async staging geometry: 4KB chunk / 128 helpers = 32B each
    const int cp_row = (tid & 127) >> 4;
    const int cp_col = ((tid & 127) & 15) * 8;
    const unsigned int dst0 = smem_u32(sh_xp + (size_t)cp_row * HD + cp_col);
    const unsigned int dst1 = dst0 + CHUNK * HD * 4;
    const float* src_base = xp + (size_t)cp_row * HD + cp_col;

    if (tid == 128) wait_flag(&g_flags[b]);
    __syncthreads();   // h init visible + first tile acquired

    if (tid >= 128) {
        cp_async16(dst0,      src_base);
        cp_async16(dst0 + 16, src_base + 4);
        cp_commit();
        cp_async16(dst1,      src_base + CHUNK * HD);
        cp_async16(dst1 + 16, src_base + CHUNK * HD + 4);
        cp_commit();
    }

#pragma unroll 1
    for (int tc = 0; tc < TQ / CHUNK; tc++) {
        cp_wait<1>();      // helpers: chunk tc landed; compute: no-op
        __syncthreads();

        if (tid < 128) {
            // -------- compute warps: 8 serial steps, R11-proven body ----
            const float* xrow = sh_xp + (size_t)(tc & 1) * CHUNK * HD + tid;
#pragma unroll 2
            for (int u = 0; u < CHUNK; u++) {
                const float xv = xrow[(size_t)u * HD];
                const ulonglong2* hp = (const ulonglong2*)(sh_h + (u & 1) * HD);

                unsigned long long a2[4] = {0ull, 0ull, 0ull, 0ull};
#pragma unroll
                for (int i = 0; i < 32; i++) {
                    ulonglong2 hv = hp[i];           // broadcast LDS
                    ffma2(a2[i & 3], hv.x, w2[2 * i]);
                    ffma2(a2[i & 3], hv.y, w2[2 * i + 1]);
                }
                unsigned long long p = addf2(addf2(a2[0], a2[1]), addf2(a2[2], a2[3]));
                float lo, hi;
                unpack2(p, lo, hi);

                const float x = lo + hi + xv;
                const float e  = __expf(2.f * x);    // tanh = 1 - 2/(e^{2x}+1)
                const float hn = 1.f - __fdividef(2.f, e + 1.f);

                sh_h[((u + 1) & 1) * HD + tid] = hn;
                __syncthreads();
            }
        } else {
            // -------- helper warps: store h one step behind + flags -----
#pragma unroll 2
            for (int u = 0; u < CHUNK; u++) {
                const int t = tc * CHUNK + u;
                if (t > 0) {
                    // h_{t-1} lives in buffer parity t&1
                    hst[(size_t)(t - 1) * HD] = sh_h[(t & 1) * HD + (tid & 127)];
                    if ((t & 63) == 0) __threadfence();        // tile rows done
                    if ((t & 63) == 1 && t > 64 && tid == 128)  // publish prev tblk
                        atomicExch(&g_flags[NTILE + ((t >> 6) - 1) * 64 + b], 1);
                }
                __syncthreads();
            }
        }

        // ---- refill just-consumed buffer with chunk tc+2 (helpers) ----
        {
            const int c2 = tc + 2;
            if ((c2 & 7) == 0 && c2 < TQ / CHUNK) {
                if (tid == 128) wait_flag(&g_flags[(c2 >> 3) * 64 + b]);
                __syncthreads();
            }
            if (tid >= 128 && c2 < TQ / CHUNK + 2) {
                const unsigned int d = (tc & 1) ? dst1 : dst0;
                const float* s = src_base + (size_t)c2 * CHUNK * HD;
                cp_async16(d,      s);
                cp_async16(d + 16, s + 4);
                cp_commit();
            }
        }
    }

    // tail: store h_{TQ-1} (in buffer parity 0) and publish last tblk
    if (tid >= 128) {
        hst[(size_t)(TQ - 1) * HD] = sh_h[0 * HD + (tid & 127)];
        __threadfence();
    }
    __syncthreads();
    if (tid == 128) atomicExch(&g_flags[NTILE + 31 * 64 + b], 1);
}

// ---------------------------------------------------------------------------
extern "C" void kernel_launch(void* const* d_in, const int* in_sizes, int n_in,
                              void* d_out, int out_size)
{
    const float* seq  = (const float*)d_in[0];
    const float* Wih  = (const float*)d_in[1];
    const float* bih  = (const float*)d_in[2];
    const float* Whh  = (const float*)d_in[3];
    const float* bhh  = (const float*)d_in[4];
    const float* Wout = (const float*)d_in[5];
    const float* bout = (const float*)d_in[6];

    float* hid = (float*)d_out;                  // hidden_states (B,T,H)
    float* out = hid + (size_t)M_TOTAL * HD;     // output_states (B,T,H)

    float* xproj;
    cudaGetSymbolAddress((void**)&xproj, g_xproj);
    void* flags;
    cudaGetSymbolAddress(&flags, g_flags);

    cudaMemsetAsync(flags, 0, 2 * NTILE * sizeof(int));
    fused_rnn_kernel<<<GRID, 256>>>(seq, Wih, bih, Whh, bhh, Wout, bout,
                                    xproj, hid, out);
}